// round 16
// baseline (speedup 1.0000x reference)
#include <cuda_runtime.h>
#include <cuda_fp16.h>
#include <math.h>
#include <stdint.h>

// ---------------- problem dims (fixed) ----------------
#define Lq   1024
#define Bq   4
#define Dq   512
#define Hq   8
#define DHq  64
#define DFFq 2048
#define ROWS 4096
#define BHq  32
#define QKV_ONE (BHq * Lq * DHq)   // 2097152
#define SROW 40                    // pg smem row stride in halves
#define QROW 72                    // flash Q/K smem stride (64+8)
#define VROW 136                   // flash V smem stride (128+8)

// ---------------- persistent scratch ----------------
__device__ __half g_xn [ROWS * Dq];
__device__ __half g_xn2[ROWS * Dq];
__device__ __half g_q[QKV_ONE], g_k[QKV_ONE];
__device__ __half g_vT[QKV_ONE];            // [bh][dh][l]  (pre-transposed)
__device__ __half g_at[ROWS * Dq];
__device__ float  g_x1[ROWS * Dq];
__device__ __half g_h1[ROWS * DFFq];
__device__ __half g_w1[1536 * 512];
__device__ __half g_w2[512 * 512];
__device__ __half g_w3[2048 * 512];
__device__ __half g_w4[512 * 2048];

// ---------------- helpers ----------------
__device__ __forceinline__ uint32_t smem_u32(const void* p) {
    uint32_t a;
    asm("{ .reg .u64 t; cvta.to.shared.u64 t, %1; cvt.u32.u64 %0, t; }" : "=r"(a) : "l"(p));
    return a;
}
__device__ __forceinline__ void cpa16(uint32_t s, const void* g) {
    asm volatile("cp.async.cg.shared.global [%0], [%1], 16;" :: "r"(s), "l"(g) : "memory");
}
__device__ __forceinline__ void mma_f16(float* d, const uint32_t* a, const uint32_t* b) {
    asm volatile(
        "mma.sync.aligned.m16n8k16.row.col.f32.f16.f16.f32 "
        "{%0,%1,%2,%3}, {%4,%5,%6,%7}, {%8,%9}, {%0,%1,%2,%3};\n"
        : "+f"(d[0]), "+f"(d[1]), "+f"(d[2]), "+f"(d[3])
        : "r"(a[0]), "r"(a[1]), "r"(a[2]), "r"(a[3]), "r"(b[0]), "r"(b[1]));
}
__device__ __forceinline__ uint32_t pack_h2(float a, float b) {
    __half2 h = __floats2half2_rn(a, b);
    return *reinterpret_cast<uint32_t*>(&h);
}

// ---------------- fp32 -> fp16 converter (all 4 weights, one launch) --------
#define W1_N4 196608   // 1536*512/4
#define W2_N4 65536    // 512*512/4
#define W3_N4 262144   // 2048*512/4
#define W4_N4 262144   // 512*2048/4
__global__ void __launch_bounds__(256) to_half_all(
    const float* __restrict__ s1, const float* __restrict__ s2,
    const float* __restrict__ s3, const float* __restrict__ s4,
    __half* __restrict__ h1, __half* __restrict__ h2,
    __half* __restrict__ h3, __half* __restrict__ h4)
{
    int i = blockIdx.x * 256 + threadIdx.x;
    const float* s; __half* h;
    if (i < W1_N4)                      { s = s1; h = h1; }
    else if (i < W1_N4 + W2_N4)         { s = s2; h = h2; i -= W1_N4; }
    else if (i < W1_N4 + W2_N4 + W3_N4) { s = s3; h = h3; i -= W1_N4 + W2_N4; }
    else                                { s = s4; h = h4; i -= W1_N4 + W2_N4 + W3_N4; }
    const float4 v = ((const float4*)s)[i];
    uint2 o;
    o.x = pack_h2(v.x, v.y);
    o.y = pack_h2(v.z, v.w);
    ((uint2*)h)[i] = o;
}

// ---------------- fp16 GEMM (R11 shape): block 128x128, 8 warps, warp 32x64 ----
// MODE 0: QKV (+bias; q,k planes; v pre-transposed)
// MODE 4: FFN1 (+bias, GELU -> fp16 plane)
template<int MODE>
__global__ void __launch_bounds__(256, 2) pg(
    const __half* __restrict__ A, const __half* __restrict__ Bm,
    const float* __restrict__ bias,
    __half* __restrict__ H0, __half* __restrict__ H1, __half* __restrict__ H2,
    int K, int astr, int bstr)
{
    extern __shared__ __half sm[];
    constexpr int PL  = 128 * SROW;
    constexpr int STG = 2 * PL;

    const int t = threadIdx.x, lane = t & 31, w = t >> 5;
    const int g = lane >> 2, tg = lane & 3;
    const int warp_m = (w >> 1) * 32, warp_n = (w & 1) * 64;
    const int row0 = blockIdx.y * 128, col0 = blockIdx.x * 128;

    const int lrow = t >> 1, lseg = (t & 1) * 16;
    const uint32_t sbase = smem_u32(sm);
    const uint32_t srow  = sbase + (uint32_t)(lrow * SROW + lseg) * 2;
    const int niter = K >> 5;

    auto issue = [&](int it) {
        if (it < niter) {
            const int k0 = it * 32;
            const size_t ao = (size_t)(row0 + lrow) * astr + k0 + lseg;
            const size_t bo = (size_t)(col0 + lrow) * bstr + k0 + lseg;
            uint32_t d = srow + (uint32_t)((it & 1) * STG) * 2;
            cpa16(d, A + ao);        cpa16(d + 16, A + ao + 8);
            d += PL * 2;
            cpa16(d, Bm + bo);       cpa16(d + 16, Bm + bo + 8);
            asm volatile("cp.async.commit_group;" ::: "memory");
        }
    };

    float c[2][8][4];
    #pragma unroll
    for (int i = 0; i < 2; i++)
        #pragma unroll
        for (int j = 0; j < 8; j++)
            #pragma unroll
            for (int q2 = 0; q2 < 4; q2++) c[i][j][q2] = 0.f;

    issue(0); issue(1);

    for (int it = 0; it < niter; it++) {
        if (it + 2 <= niter) asm volatile("cp.async.wait_group 1;" ::: "memory");
        else                 asm volatile("cp.async.wait_group 0;" ::: "memory");
        __syncthreads();

        const __half* AS = sm + (it & 1) * STG;
        const __half* BS = AS + PL;

        #pragma unroll
        for (int kk = 0; kk < 32; kk += 16) {
            uint32_t ah[2][4];
            #pragma unroll
            for (int mi = 0; mi < 2; mi++) {
                const int rb = (warp_m + mi * 16 + g) * SROW + kk + tg * 2;
                ah[mi][0] = *(const uint32_t*)(AS + rb);
                ah[mi][1] = *(const uint32_t*)(AS + rb + 8 * SROW);
                ah[mi][2] = *(const uint32_t*)(AS + rb + 8);
                ah[mi][3] = *(const uint32_t*)(AS + rb + 8 * SROW + 8);
            }
            #pragma unroll
            for (int ni = 0; ni < 8; ni++) {
                const int nb = (warp_n + ni * 8 + g) * SROW + kk + tg * 2;
                uint32_t bh[2];
                bh[0] = *(const uint32_t*)(BS + nb);
                bh[1] = *(const uint32_t*)(BS + nb + 8);
                mma_f16(c[0][ni], ah[0], bh);
                mma_f16(c[1][ni], ah[1], bh);
            }
        }
        __syncthreads();
        issue(it + 2);
    }

    #pragma unroll
    for (int mi = 0; mi < 2; mi++)
    #pragma unroll
    for (int ni = 0; ni < 8; ni++) {
        const int cg = col0 + warp_n + ni * 8 + tg * 2;
        #pragma unroll
        for (int hf = 0; hf < 2; hf++) {
            const int r = row0 + warp_m + mi * 16 + g + hf * 8;
            float v0 = c[mi][ni][hf * 2 + 0];
            float v1 = c[mi][ni][hf * 2 + 1];

            if (MODE == 0) {
                const float2 bb = *(const float2*)(bias + cg);
                v0 += bb.x; v1 += bb.y;
                const int which = cg >> 9, cc = cg & 511, h = cc >> 6, dh0 = cc & 63;
                const int l = r >> 2, b = r & 3;
                const int bh = b * Hq + h;
                if (which == 2) {
                    H2[((size_t)bh * DHq + dh0)     * Lq + l] = __float2half_rn(v0);
                    H2[((size_t)bh * DHq + dh0 + 1) * Lq + l] = __float2half_rn(v1);
                } else {
                    const size_t o = ((size_t)bh * Lq + l) * DHq + dh0;
                    __half* dst = (which == 0) ? H0 : H1;
                    *(uint32_t*)(dst + o) = pack_h2(v0, v1);
                }
            } else {   // MODE 4
                const float2 bb = *(const float2*)(bias + cg);
                v0 += bb.x; v1 += bb.y;
                v0 = 0.5f * v0 * (1.f + erff(v0 * 0.70710678118654752f));
                v1 = 0.5f * v1 * (1.f + erff(v1 * 0.70710678118654752f));
                *(uint32_t*)(H0 + (size_t)r * DFFq + cg) = pack_h2(v0, v1);
            }
        }
    }
}

// ---------------- pg64: 64x128 block, 8 warps (2m x 4n, warp 32x32) ----------
// bias + residual -> fp32. Used for out-proj and FFN2 (grid 4 x 64 = 256 CTAs).
__global__ void __launch_bounds__(256, 3) pg64(
    const __half* __restrict__ A, const __half* __restrict__ Bm,
    const float* __restrict__ bias, const float* __restrict__ extra,
    float* __restrict__ Cf, int K)
{
    extern __shared__ __half sm[];
    constexpr int PLA = 64 * SROW;
    constexpr int PLB = 128 * SROW;
    constexpr int STG = PLA + PLB;

    const int t = threadIdx.x, lane = t & 31, w = t >> 5;
    const int g = lane >> 2, tg = lane & 3;
    const int warp_m = (w >> 2) * 32, warp_n = (w & 3) * 32;
    const int row0 = blockIdx.y * 64, col0 = blockIdx.x * 128;

    const uint32_t sbase = smem_u32(sm);
    const int arow = t >> 2, aseg = (t & 3) * 8;        // A: 64 rows x 4 segs
    const int brow = t >> 1, bseg = (t & 1) * 16;       // B: 128 rows x 2 segs
    const uint32_t sa = sbase + (uint32_t)(arow * SROW + aseg) * 2;
    const uint32_t sb = sbase + (uint32_t)(PLA + brow * SROW + bseg) * 2;
    const int niter = K >> 5;

    auto issue = [&](int it) {
        if (it < niter) {
            const int k0 = it * 32;
            const uint32_t off = (uint32_t)((it & 1) * STG) * 2;
            cpa16(sa + off, A + (size_t)(row0 + arow) * K + k0 + aseg);
            const __half* bp = Bm + (size_t)(col0 + brow) * K + k0 + bseg;
            cpa16(sb + off, bp);
            cpa16(sb + off + 16, bp + 8);
            asm volatile("cp.async.commit_group;" ::: "memory");
        }
    };

    float c[2][4][4];
    #pragma unroll
    for (int i = 0; i < 2; i++)
        #pragma unroll
        for (int j = 0; j < 4; j++)
            #pragma unroll
            for (int q2 = 0; q2 < 4; q2++) c[i][j][q2] = 0.f;

    issue(0); issue(1);

    for (int it = 0; it < niter; it++) {
        if (it + 2 <= niter) asm volatile("cp.async.wait_group 1;" ::: "memory");
        else                 asm volatile("cp.async.wait_group 0;" ::: "memory");
        __syncthreads();

        const __half* AS = sm + (it & 1) * STG;
        const __half* BS = AS + PLA;

        #pragma unroll
        for (int kk = 0; kk < 32; kk += 16) {
            uint32_t ah[2][4];
            #pragma unroll
            for (int mi = 0; mi < 2; mi++) {
                const int rb = (warp_m + mi * 16 + g) * SROW + kk + tg * 2;
                ah[mi][0] = *(const uint32_t*)(AS + rb);
                ah[mi][1] = *(const uint32_t*)(AS + rb + 8 * SROW);
                ah[mi][2] = *(const uint32_t*)(AS + rb + 8);
                ah[mi][3] = *(const uint32_t*)(AS + rb + 8 * SROW + 8);
            }
            #pragma unroll
            for (int ni = 0; ni < 4; ni++) {
                const int nb = (warp_n + ni * 8 + g) * SROW + kk + tg * 2;
                uint32_t bh[2];
                bh[0] = *(const uint32_t*)(BS + nb);
                bh[1] = *(const uint32_t*)(BS + nb + 8);
                mma_f16(c[0][ni], ah[0], bh);
                mma_f16(c[1][ni], ah[1], bh);
            }
        }
        __syncthreads();
        issue(it + 2);
    }

    #pragma unroll
    for (int mi = 0; mi < 2; mi++)
    #pragma unroll
    for (int ni = 0; ni < 4; ni++) {
        const int cg = col0 + warp_n + ni * 8 + tg * 2;
        const float2 bb = *(const float2*)(bias + cg);
        #pragma unroll
        for (int hf = 0; hf < 2; hf++) {
            const int r = row0 + warp_m + mi * 16 + g + hf * 8;
            const size_t o = (size_t)r * Dq + cg;
            const float2 e = *(const float2*)(extra + o);
            *(float2*)(Cf + o) = make_float2(c[mi][ni][hf * 2] + bb.x + e.x,
                                             c[mi][ni][hf * 2 + 1] + bb.y + e.y);
        }
    }
}

// ---------------- flash attention (exact R11/R15 body) ----------------
__global__ void __launch_bounds__(256) flash(
    const __half* __restrict__ Q, const __half* __restrict__ Kg,
    const __half* __restrict__ VT,
    const float* __restrict__ edge, float* __restrict__ edge_out,
    __half* __restrict__ O)
{
    extern __shared__ __half sm[];
    __half* Qs = sm;                         // 128 x QROW
    __half* Ks = Qs + 128 * QROW;            // 2 stages x 128 x QROW
    __half* Vs = Ks + 2 * 128 * QROW;        // 2 stages x 64 x VROW

    const int t = threadIdx.x, lane = t & 31, w = t >> 5;
    const int g = lane >> 2, tg = lane & 3;
    const int z = blockIdx.y, row0 = blockIdx.x * 128;
    const int bb_ = z >> 3, hh_ = z & 7;

    const __half* Qp = Q  + (size_t)z * Lq * DHq;
    const __half* Kp = Kg + (size_t)z * Lq * DHq;
    const __half* Vp = VT + (size_t)z * DHq * Lq;

    const uint32_t qs_u = smem_u32(Qs);
    const uint32_t ks_u = smem_u32(Ks);
    const uint32_t vs_u = smem_u32(Vs);

    const int qrow = t >> 1, qcol = (t & 1) * 32;
    const int vrow = t >> 2, vcol = (t & 3) * 32;

    auto issue = [&](int ct, bool withQ) {
        if (ct < 8) {
            const int s = ct & 1;
            const int c0 = ct * 128;
            if (withQ) {
                #pragma unroll
                for (int j = 0; j < 4; j++)
                    cpa16(qs_u + (uint32_t)(qrow * QROW + qcol + j * 8) * 2,
                          Qp + (size_t)(row0 + qrow) * DHq + qcol + j * 8);
            }
            #pragma unroll
            for (int j = 0; j < 4; j++)
                cpa16(ks_u + (uint32_t)(s * 128 * QROW + qrow * QROW + qcol + j * 8) * 2,
                      Kp + (size_t)(c0 + qrow) * DHq + qcol + j * 8);
            #pragma unroll
            for (int j = 0; j < 4; j++)
                cpa16(vs_u + (uint32_t)(s * 64 * VROW + vrow * VROW + vcol + j * 8) * 2,
                      Vp + (size_t)vrow * Lq + c0 + vcol + j * 8);
            asm volatile("cp.async.commit_group;" ::: "memory");
        }
    };

    issue(0, true); issue(1, false);

    uint32_t qa[4][4];
    float oc[8][4];
    #pragma unroll
    for (int dt = 0; dt < 8; dt++)
        #pragma unroll
        for (int j = 0; j < 4; j++) oc[dt][j] = 0.f;
    float m0 = -1e30f, m1 = -1e30f, l0 = 0.f, l1 = 0.f;

    const int r0 = row0 + w * 16 + g;
    const int r1 = r0 + 8;

    for (int ct = 0; ct < 8; ct++) {
        if (ct + 2 <= 8) asm volatile("cp.async.wait_group 1;" ::: "memory");
        else             asm volatile("cp.async.wait_group 0;" ::: "memory");
        __syncthreads();

        if (ct == 0) {
            #pragma unroll
            for (int ki = 0; ki < 4; ki++) {
                const int rb = (w * 16 + g) * QROW + ki * 16 + tg * 2;
                qa[ki][0] = *(const uint32_t*)(Qs + rb);
                qa[ki][1] = *(const uint32_t*)(Qs + rb + 8 * QROW);
                qa[ki][2] = *(const uint32_t*)(Qs + rb + 8);
                qa[ki][3] = *(const uint32_t*)(Qs + rb + 8 * QROW + 8);
            }
        }

        const __half* KS = Ks + (ct & 1) * 128 * QROW;
        const __half* VS = Vs + (ct & 1) * 64 * VROW;
        const int c0 = ct * 128;

        #pragma unroll
        for (int sub = 0; sub < 2; sub++) {
            float sf[8][4];
            #pragma unroll
            for (int nt = 0; nt < 8; nt++) {
                sf[nt][0] = sf[nt][1] = sf[nt][2] = sf[nt][3] = 0.f;
                const int nrow = (sub * 64 + nt * 8 + g) * QROW + tg * 2;
                #pragma unroll
                for (int ki = 0; ki < 4; ki++) {
                    uint32_t bh2[2];
                    bh2[0] = *(const uint32_t*)(KS + nrow + ki * 16);
                    bh2[1] = *(const uint32_t*)(KS + nrow + ki * 16 + 8);
                    mma_f16(sf[nt], qa[ki], bh2);
                }
            }
            #pragma unroll
            for (int nt = 0; nt < 8; nt++) {
                const int col = c0 + sub * 64 + nt * 8 + tg * 2;
                const size_t e0 = ((size_t)z * Lq + r0) * Lq + col;
                const size_t e1 = ((size_t)z * Lq + r1) * Lq + col;
                const float2 ea = *(const float2*)(edge + e0);
                const float2 eb = *(const float2*)(edge + e1);
                sf[nt][0] = sf[nt][0] * 0.125f + ea.x;
                sf[nt][1] = sf[nt][1] * 0.125f + ea.y;
                sf[nt][2] = sf[nt][2] * 0.125f + eb.x;
                sf[nt][3] = sf[nt][3] * 0.125f + eb.y;
                *(float2*)(edge_out + e0) = make_float2(sf[nt][0], sf[nt][1]);
                *(float2*)(edge_out + e1) = make_float2(sf[nt][2], sf[nt][3]);
            }
            float tm0 = -1e30f, tm1 = -1e30f;
            #pragma unroll
            for (int nt = 0; nt < 8; nt++) {
                tm0 = fmaxf(tm0, fmaxf(sf[nt][0], sf[nt][1]));
                tm1 = fmaxf(tm1, fmaxf(sf[nt][2], sf[nt][3]));
            }
            tm0 = fmaxf(tm0, __shfl_xor_sync(0xffffffffu, tm0, 1));
            tm0 = fmaxf(tm0, __shfl_xor_sync(0xffffffffu, tm0, 2));
            tm1 = fmaxf(tm1, __shfl_xor_sync(0xffffffffu, tm1, 1));
            tm1 = fmaxf(tm1, __shfl_xor_sync(0xffffffffu, tm1, 2));
            const float m0n = fmaxf(m0, tm0), m1n = fmaxf(m1, tm1);
            const float a0 = expf(m0 - m0n), a1 = expf(m1 - m1n);
            m0 = m0n; m1 = m1n;
            float rs0 = 0.f, rs1 = 0.f;
            #pragma unroll
            for (int nt = 0; nt < 8; nt++) {
                sf[nt][0] = expf(sf[nt][0] - m0n);
                sf[nt][1] = expf(sf[nt][1] - m0n);
                sf[nt][2] = expf(sf[nt][2] - m1n);
                sf[nt][3] = expf(sf[nt][3] - m1n);
                rs0 += sf[nt][0] + sf[nt][1];
                rs1 += sf[nt][2] + sf[nt][3];
            }
            rs0 += __shfl_xor_sync(0xffffffffu, rs0, 1);
            rs0 += __shfl_xor_sync(0xffffffffu, rs0, 2);
            rs1 += __shfl_xor_sync(0xffffffffu, rs1, 1);
            rs1 += __shfl_xor_sync(0xffffffffu, rs1, 2);
            l0 = a0 * l0 + rs0;
            l1 = a1 * l1 + rs1;
            #pragma unroll
            for (int dt = 0; dt < 8; dt++) {
                oc[dt][0] *= a0; oc[dt][1] *= a0;
                oc[dt][2] *= a1; oc[dt][3] *= a1;
            }
            #pragma unroll
            for (int ki = 0; ki < 4; ki++) {
                uint32_t pa[4];
                pa[0] = pack_h2(sf[2*ki][0],   sf[2*ki][1]);
                pa[1] = pack_h2(sf[2*ki][2],   sf[2*ki][3]);
                pa[2] = pack_h2(sf[2*ki+1][0], sf[2*ki+1][1]);
                pa[3] = pack_h2(sf[2*ki+1][2], sf[2*ki+1][3]);
                #pragma unroll
                for (int dt = 0; dt < 8; dt++) {
                    const int nb = (dt * 8 + g) * VROW + sub * 64 + ki * 16 + tg * 2;
                    uint32_t vb[2];
                    vb[0] = *(const uint32_t*)(VS + nb);
                    vb[1] = *(const uint32_t*)(VS + nb + 8);
                    mma_f16(oc[dt], pa, vb);
                }
            }
        }
        __syncthreads();
        issue(ct + 2, false);
    }

    const float il0 = 1.f / l0, il1 = 1.f / l1;
    #pragma unroll
    for (int dt = 0; dt < 8; dt++) {
        const int dh = hh_ * DHq + dt * 8 + tg * 2;
        *(uint32_t*)(O + ((size_t)r0 * Bq + bb_) * Dq + dh) =
            pack_h2(oc[dt][0] * il0, oc[dt][1] * il0);
        *(uint32_t*)(O + ((size_t)r1 * Bq + bb_) * Dq + dh) =
            pack_h2(oc[dt][2] * il1, oc[dt][3] * il1);
    }
}

// ---------------- LayerNorm -> fp16 plane ----------------
__global__ void __launch_bounds__(128) ln_kernel(
    const float* __restrict__ x, const float* __restrict__ w,
    const float* __restrict__ b, __half* __restrict__ y)
{
    const int row = blockIdx.x;
    const int t = threadIdx.x;
    const float4 v = ((const float4*)(x + (size_t)row * Dq))[t];
    float s  = v.x + v.y + v.z + v.w;
    float ss = v.x*v.x + v.y*v.y + v.z*v.z + v.w*v.w;
#pragma unroll
    for (int o = 16; o > 0; o >>= 1) {
        s  += __shfl_xor_sync(0xffffffffu, s,  o);
        ss += __shfl_xor_sync(0xffffffffu, ss, o);
    }
    __shared__ float sh[8];
    const int wi = t >> 5, lane = t & 31;
    if (lane == 0) { sh[wi] = s; sh[4 + wi] = ss; }
    __syncthreads();
    s  = sh[0] + sh[1] + sh[2] + sh[3];
    ss = sh[4] + sh[5] + sh[6] + sh[7];
    const float mu  = s * (1.f / Dq);
    const float var = ss * (1.f / Dq) - mu * mu;
    const float rs  = rsqrtf(var + 1e-5f);
    const float4 wv = ((const float4*)w)[t];
    const float4 bv = ((const float4*)b)[t];
    uint2 o;
    o.x = pack_h2((v.x - mu) * rs * wv.x + bv.x, (v.y - mu) * rs * wv.y + bv.y);
    o.y = pack_h2((v.z - mu) * rs * wv.z + bv.z, (v.w - mu) * rs * wv.w + bv.w);
    ((uint2*)(y + (size_t)row * Dq))[t] = o;
}

// ---------------- launch ----------------
extern "C" void kernel_launch(void* const* d_in, const int* in_sizes, int n_in,
                              void* d_out, int out_size)
{
    (void)in_sizes; (void)n_in; (void)out_size;
    const float* x    = (const float*)d_in[0];
    const float* edge = (const float*)d_in[1];
    const float* inw  = (const float*)d_in[2];
    const float* inb  = (const float*)d_in[3];
    const float* outw = (const float*)d_in[4];
    const float* outb = (const float*)d_in[5];
    const float* l1w  = (const float*)d_in[6];
    const float* l1b  = (const float*)d_in[7];
    const float* l2w  = (const float*)d_in[8];
    const float* l2b  = (const float*)d_in[9];
    const float* n1w  = (const float*)d_in[10];
    const float* n1b  = (const float*)d_in[11];
    const float* n2w  = (const float*)d_in[12];
    const float* n2b  = (const float*)d_in[13];

    __half *xn,*xn2,*q,*k,*vT,*at,*h1,*w1,*w2,*w3,*w4;
    float *x1;
    cudaGetSymbolAddress((void**)&xn,   g_xn);
    cudaGetSymbolAddress((void**)&xn2,  g_xn2);
    cudaGetSymbolAddress((void**)&q,    g_q);
    cudaGetSymbolAddress((void**)&k,    g_k);
    cudaGetSymbolAddress((void**)&vT,   g_vT);
    cudaGetSymbolAddress((void**)&at,   g_at);
    cudaGetSymbolAddress((void**)&h1,   g_h1);
    cudaGetSymbolAddress((void**)&w1,   g_w1);
    cudaGetSymbolAddress((void**)&w2,   g_w2);
    cudaGetSymbolAddress((void**)&w3,   g_w3);
    cudaGetSymbolAddress((void**)&w4,   g_w4);
    cudaGetSymbolAddress((void**)&x1,   g_x1);

    float* out_x    = (float*)d_out;
    float* edge_out = out_x + (size_t)ROWS * Dq;

    const int PG_SMEM  = 2 * 2 * 128 * SROW * (int)sizeof(__half);                   // 40960
    const int PG64_SMEM = 2 * (64 + 128) * SROW * (int)sizeof(__half);               // 30720
    const int FL_SMEM  = (128 * QROW + 2 * 128 * QROW + 2 * 64 * VROW) * (int)sizeof(__half); // 90112
    cudaFuncSetAttribute(pg<0>, cudaFuncAttributeMaxDynamicSharedMemorySize, PG_SMEM);
    cudaFuncSetAttribute(pg<4>, cudaFuncAttributeMaxDynamicSharedMemorySize, PG_SMEM);
    cudaFuncSetAttribute(pg64,  cudaFuncAttributeMaxDynamicSharedMemorySize, PG64_SMEM);
    cudaFuncSetAttribute(flash, cudaFuncAttributeMaxDynamicSharedMemorySize, FL_SMEM);

    // 0) all weights -> fp16 in one launch
    to_half_all<<<(W1_N4 + W2_N4 + W3_N4 + W4_N4) / 256, 256>>>(
        inw, outw, l1w, l2w, w1, w2, w3, w4);
    // 1) LN1
    ln_kernel<<<ROWS, 128>>>(x, n1w, n1b, xn);
    // 2) QKV (q,k planes; v transposed)
    pg<0><<<dim3(12, 32, 1), 256, PG_SMEM>>>(xn, w1, inb, q, k, vT, Dq, Dq, Dq);
    // 3) fused attention: edge_out + attn plane
    flash<<<dim3(8, BHq), 256, FL_SMEM>>>(q, k, vT, edge, edge_out, at);
    // 4) out projection + residual  (64-row tiles, 256 CTAs)
    pg64<<<dim3(4, 64, 1), 256, PG64_SMEM>>>(at, w2, outb, x, x1, Dq);
    // 5) LN2
    ln_kernel<<<ROWS, 128>>>(x1, n2w, n2b, xn2);
    // 6) FFN1 + GELU
    pg<4><<<dim3(16, 32, 1), 256, PG_SMEM>>>(xn2, w3, l1b, h1, nullptr, nullptr, Dq, Dq, Dq);
    // 7) FFN2 + residual -> final x  (64-row tiles, 256 CTAs)
    pg64<<<dim3(4, 64, 1), 256, PG64_SMEM>>>(h1, w4, l2b, x1, out_x, DFFq);
}

// round 17
// speedup vs baseline: 1.0251x; 1.0251x over previous
#include <cuda_runtime.h>
#include <cuda_fp16.h>
#include <math.h>
#include <stdint.h>

// ---------------- problem dims (fixed) ----------------
#define Lq   1024
#define Bq   4
#define Dq   512
#define Hq   8
#define DHq  64
#define DFFq 2048
#define ROWS 4096
#define BHq  32
#define QKV_ONE (BHq * Lq * DHq)   // 2097152
#define SROW 40                    // pg smem row stride in halves
#define QROW 72                    // flash Q/K smem stride (64+8)
#define VROW 136                   // flash V smem stride (128+8)

// ---------------- persistent scratch ----------------
__device__ __half g_xn [ROWS * Dq];
__device__ __half g_xn2[ROWS * Dq];
__device__ __half g_q[QKV_ONE], g_k[QKV_ONE];
__device__ __half g_vT[QKV_ONE];            // [bh][dh][l]  (pre-transposed)
__device__ __half g_at[ROWS * Dq];
__device__ float  g_x1[ROWS * Dq];
__device__ __half g_h1[ROWS * DFFq];
__device__ __half g_w1[1536 * 512];
__device__ __half g_w2[512 * 512];
__device__ __half g_w3[2048 * 512];
__device__ __half g_w4[512 * 2048];

// ---------------- helpers ----------------
__device__ __forceinline__ uint32_t smem_u32(const void* p) {
    uint32_t a;
    asm("{ .reg .u64 t; cvta.to.shared.u64 t, %1; cvt.u32.u64 %0, t; }" : "=r"(a) : "l"(p));
    return a;
}
__device__ __forceinline__ void cpa16(uint32_t s, const void* g) {
    asm volatile("cp.async.cg.shared.global [%0], [%1], 16;" :: "r"(s), "l"(g) : "memory");
}
__device__ __forceinline__ void mma_f16(float* d, const uint32_t* a, const uint32_t* b) {
    asm volatile(
        "mma.sync.aligned.m16n8k16.row.col.f32.f16.f16.f32 "
        "{%0,%1,%2,%3}, {%4,%5,%6,%7}, {%8,%9}, {%0,%1,%2,%3};\n"
        : "+f"(d[0]), "+f"(d[1]), "+f"(d[2]), "+f"(d[3])
        : "r"(a[0]), "r"(a[1]), "r"(a[2]), "r"(a[3]), "r"(b[0]), "r"(b[1]));
}
__device__ __forceinline__ uint32_t pack_h2(float a, float b) {
    __half2 h = __floats2half2_rn(a, b);
    return *reinterpret_cast<uint32_t*>(&h);
}

// ---------------- fp32 -> fp16 converter (all 4 weights, one launch) --------
#define W1_N4 196608   // 1536*512/4
#define W2_N4 65536    // 512*512/4
#define W3_N4 262144   // 2048*512/4
#define W4_N4 262144   // 512*2048/4
__global__ void __launch_bounds__(256) to_half_all(
    const float* __restrict__ s1, const float* __restrict__ s2,
    const float* __restrict__ s3, const float* __restrict__ s4,
    __half* __restrict__ h1, __half* __restrict__ h2,
    __half* __restrict__ h3, __half* __restrict__ h4)
{
    int i = blockIdx.x * 256 + threadIdx.x;
    const float* s; __half* h;
    if (i < W1_N4)                      { s = s1; h = h1; }
    else if (i < W1_N4 + W2_N4)         { s = s2; h = h2; i -= W1_N4; }
    else if (i < W1_N4 + W2_N4 + W3_N4) { s = s3; h = h3; i -= W1_N4 + W2_N4; }
    else                                { s = s4; h = h4; i -= W1_N4 + W2_N4 + W3_N4; }
    const float4 v = ((const float4*)s)[i];
    uint2 o;
    o.x = pack_h2(v.x, v.y);
    o.y = pack_h2(v.z, v.w);
    ((uint2*)h)[i] = o;
}

// ---------------- fp16 GEMM (R11 shape): block 128x128, 8 warps, warp 32x64 ----
// MODE 0: QKV (+bias; q,k planes; v pre-transposed)
// MODE 4: FFN1 (+bias, GELU -> fp16 plane)
// MODE 6: split-K (grid.z splits; epilogue atomicAdd into pre-initialized Cf)
template<int MODE>
__global__ void __launch_bounds__(256, 2) pg(
    const __half* __restrict__ A, const __half* __restrict__ Bm,
    const float* __restrict__ bias, float* __restrict__ Cf,
    __half* __restrict__ H0, __half* __restrict__ H1, __half* __restrict__ H2,
    int K, int astr, int bstr)
{
    extern __shared__ __half sm[];
    constexpr int PL  = 128 * SROW;
    constexpr int STG = 2 * PL;

    const int t = threadIdx.x, lane = t & 31, w = t >> 5;
    const int g = lane >> 2, tg = lane & 3;
    const int warp_m = (w >> 1) * 32, warp_n = (w & 1) * 64;
    const int row0 = blockIdx.y * 128, col0 = blockIdx.x * 128;

    const int Keff  = (MODE == 6) ? (K >> 1) : K;
    const int kbase = (MODE == 6) ? (blockIdx.z * Keff) : 0;

    const int lrow = t >> 1, lseg = (t & 1) * 16;
    const uint32_t sbase = smem_u32(sm);
    const uint32_t srow  = sbase + (uint32_t)(lrow * SROW + lseg) * 2;
    const int niter = Keff >> 5;

    auto issue = [&](int it) {
        if (it < niter) {
            const int k0 = kbase + it * 32;
            const size_t ao = (size_t)(row0 + lrow) * astr + k0 + lseg;
            const size_t bo = (size_t)(col0 + lrow) * bstr + k0 + lseg;
            uint32_t d = srow + (uint32_t)((it & 1) * STG) * 2;
            cpa16(d, A + ao);        cpa16(d + 16, A + ao + 8);
            d += PL * 2;
            cpa16(d, Bm + bo);       cpa16(d + 16, Bm + bo + 8);
            asm volatile("cp.async.commit_group;" ::: "memory");
        }
    };

    float c[2][8][4];
    #pragma unroll
    for (int i = 0; i < 2; i++)
        #pragma unroll
        for (int j = 0; j < 8; j++)
            #pragma unroll
            for (int q2 = 0; q2 < 4; q2++) c[i][j][q2] = 0.f;

    issue(0); issue(1);

    for (int it = 0; it < niter; it++) {
        if (it + 2 <= niter) asm volatile("cp.async.wait_group 1;" ::: "memory");
        else                 asm volatile("cp.async.wait_group 0;" ::: "memory");
        __syncthreads();

        const __half* AS = sm + (it & 1) * STG;
        const __half* BS = AS + PL;

        #pragma unroll
        for (int kk = 0; kk < 32; kk += 16) {
            uint32_t ah[2][4];
            #pragma unroll
            for (int mi = 0; mi < 2; mi++) {
                const int rb = (warp_m + mi * 16 + g) * SROW + kk + tg * 2;
                ah[mi][0] = *(const uint32_t*)(AS + rb);
                ah[mi][1] = *(const uint32_t*)(AS + rb + 8 * SROW);
                ah[mi][2] = *(const uint32_t*)(AS + rb + 8);
                ah[mi][3] = *(const uint32_t*)(AS + rb + 8 * SROW + 8);
            }
            #pragma unroll
            for (int ni = 0; ni < 8; ni++) {
                const int nb = (warp_n + ni * 8 + g) * SROW + kk + tg * 2;
                uint32_t bh[2];
                bh[0] = *(const uint32_t*)(BS + nb);
                bh[1] = *(const uint32_t*)(BS + nb + 8);
                mma_f16(c[0][ni], ah[0], bh);
                mma_f16(c[1][ni], ah[1], bh);
            }
        }
        __syncthreads();
        issue(it + 2);
    }

    #pragma unroll
    for (int mi = 0; mi < 2; mi++)
    #pragma unroll
    for (int ni = 0; ni < 8; ni++) {
        const int cg = col0 + warp_n + ni * 8 + tg * 2;
        #pragma unroll
        for (int hf = 0; hf < 2; hf++) {
            const int r = row0 + warp_m + mi * 16 + g + hf * 8;
            float v0 = c[mi][ni][hf * 2 + 0];
            float v1 = c[mi][ni][hf * 2 + 1];

            if (MODE == 0) {
                const float2 bb = *(const float2*)(bias + cg);
                v0 += bb.x; v1 += bb.y;
                const int which = cg >> 9, cc = cg & 511, h = cc >> 6, dh0 = cc & 63;
                const int l = r >> 2, b = r & 3;
                const int bh = b * Hq + h;
                if (which == 2) {
                    H2[((size_t)bh * DHq + dh0)     * Lq + l] = __float2half_rn(v0);
                    H2[((size_t)bh * DHq + dh0 + 1) * Lq + l] = __float2half_rn(v1);
                } else {
                    const size_t o = ((size_t)bh * Lq + l) * DHq + dh0;
                    __half* dst = (which == 0) ? H0 : H1;
                    *(uint32_t*)(dst + o) = pack_h2(v0, v1);
                }
            } else if (MODE == 4) {
                const float2 bb = *(const float2*)(bias + cg);
                v0 += bb.x; v1 += bb.y;
                v0 = 0.5f * v0 * (1.f + erff(v0 * 0.70710678118654752f));
                v1 = 0.5f * v1 * (1.f + erff(v1 * 0.70710678118654752f));
                *(uint32_t*)(H0 + (size_t)r * DFFq + cg) = pack_h2(v0, v1);
            } else {   // MODE 6: atomic accumulate into pre-initialized target
                const size_t o = (size_t)r * Dq + cg;
                atomicAdd(Cf + o, v0);
                atomicAdd(Cf + o + 1, v1);
            }
        }
    }
}

// ---------------- flash attention (exact R11/R15 body) ----------------
__global__ void __launch_bounds__(256) flash(
    const __half* __restrict__ Q, const __half* __restrict__ Kg,
    const __half* __restrict__ VT,
    const float* __restrict__ edge, float* __restrict__ edge_out,
    __half* __restrict__ O)
{
    extern __shared__ __half sm[];
    __half* Qs = sm;                         // 128 x QROW
    __half* Ks = Qs + 128 * QROW;            // 2 stages x 128 x QROW
    __half* Vs = Ks + 2 * 128 * QROW;        // 2 stages x 64 x VROW

    const int t = threadIdx.x, lane = t & 31, w = t >> 5;
    const int g = lane >> 2, tg = lane & 3;
    const int z = blockIdx.y, row0 = blockIdx.x * 128;
    const int bb_ = z >> 3, hh_ = z & 7;

    const __half* Qp = Q  + (size_t)z * Lq * DHq;
    const __half* Kp = Kg + (size_t)z * Lq * DHq;
    const __half* Vp = VT + (size_t)z * DHq * Lq;

    const uint32_t qs_u = smem_u32(Qs);
    const uint32_t ks_u = smem_u32(Ks);
    const uint32_t vs_u = smem_u32(Vs);

    const int qrow = t >> 1, qcol = (t & 1) * 32;
    const int vrow = t >> 2, vcol = (t & 3) * 32;

    auto issue = [&](int ct, bool withQ) {
        if (ct < 8) {
            const int s = ct & 1;
            const int c0 = ct * 128;
            if (withQ) {
                #pragma unroll
                for (int j = 0; j < 4; j++)
                    cpa16(qs_u + (uint32_t)(qrow * QROW + qcol + j * 8) * 2,
                          Qp + (size_t)(row0 + qrow) * DHq + qcol + j * 8);
            }
            #pragma unroll
            for (int j = 0; j < 4; j++)
                cpa16(ks_u + (uint32_t)(s * 128 * QROW + qrow * QROW + qcol + j * 8) * 2,
                      Kp + (size_t)(c0 + qrow) * DHq + qcol + j * 8);
            #pragma unroll
            for (int j = 0; j < 4; j++)
                cpa16(vs_u + (uint32_t)(s * 64 * VROW + vrow * VROW + vcol + j * 8) * 2,
                      Vp + (size_t)vrow * Lq + c0 + vcol + j * 8);
            asm volatile("cp.async.commit_group;" ::: "memory");
        }
    };

    issue(0, true); issue(1, false);

    uint32_t qa[4][4];
    float oc[8][4];
    #pragma unroll
    for (int dt = 0; dt < 8; dt++)
        #pragma unroll
        for (int j = 0; j < 4; j++) oc[dt][j] = 0.f;
    float m0 = -1e30f, m1 = -1e30f, l0 = 0.f, l1 = 0.f;

    const int r0 = row0 + w * 16 + g;
    const int r1 = r0 + 8;

    for (int ct = 0; ct < 8; ct++) {
        if (ct + 2 <= 8) asm volatile("cp.async.wait_group 1;" ::: "memory");
        else             asm volatile("cp.async.wait_group 0;" ::: "memory");
        __syncthreads();

        if (ct == 0) {
            #pragma unroll
            for (int ki = 0; ki < 4; ki++) {
                const int rb = (w * 16 + g) * QROW + ki * 16 + tg * 2;
                qa[ki][0] = *(const uint32_t*)(Qs + rb);
                qa[ki][1] = *(const uint32_t*)(Qs + rb + 8 * QROW);
                qa[ki][2] = *(const uint32_t*)(Qs + rb + 8);
                qa[ki][3] = *(const uint32_t*)(Qs + rb + 8 * QROW + 8);
            }
        }

        const __half* KS = Ks + (ct & 1) * 128 * QROW;
        const __half* VS = Vs + (ct & 1) * 64 * VROW;
        const int c0 = ct * 128;

        #pragma unroll
        for (int sub = 0; sub < 2; sub++) {
            float sf[8][4];
            #pragma unroll
            for (int nt = 0; nt < 8; nt++) {
                sf[nt][0] = sf[nt][1] = sf[nt][2] = sf[nt][3] = 0.f;
                const int nrow = (sub * 64 + nt * 8 + g) * QROW + tg * 2;
                #pragma unroll
                for (int ki = 0; ki < 4; ki++) {
                    uint32_t bh2[2];
                    bh2[0] = *(const uint32_t*)(KS + nrow + ki * 16);
                    bh2[1] = *(const uint32_t*)(KS + nrow + ki * 16 + 8);
                    mma_f16(sf[nt], qa[ki], bh2);
                }
            }
            #pragma unroll
            for (int nt = 0; nt < 8; nt++) {
                const int col = c0 + sub * 64 + nt * 8 + tg * 2;
                const size_t e0 = ((size_t)z * Lq + r0) * Lq + col;
                const size_t e1 = ((size_t)z * Lq + r1) * Lq + col;
                const float2 ea = *(const float2*)(edge + e0);
                const float2 eb = *(const float2*)(edge + e1);
                sf[nt][0] = sf[nt][0] * 0.125f + ea.x;
                sf[nt][1] = sf[nt][1] * 0.125f + ea.y;
                sf[nt][2] = sf[nt][2] * 0.125f + eb.x;
                sf[nt][3] = sf[nt][3] * 0.125f + eb.y;
                *(float2*)(edge_out + e0) = make_float2(sf[nt][0], sf[nt][1]);
                *(float2*)(edge_out + e1) = make_float2(sf[nt][2], sf[nt][3]);
            }
            float tm0 = -1e30f, tm1 = -1e30f;
            #pragma unroll
            for (int nt = 0; nt < 8; nt++) {
                tm0 = fmaxf(tm0, fmaxf(sf[nt][0], sf[nt][1]));
                tm1 = fmaxf(tm1, fmaxf(sf[nt][2], sf[nt][3]));
            }
            tm0 = fmaxf(tm0, __shfl_xor_sync(0xffffffffu, tm0, 1));
            tm0 = fmaxf(tm0, __shfl_xor_sync(0xffffffffu, tm0, 2));
            tm1 = fmaxf(tm1, __shfl_xor_sync(0xffffffffu, tm1, 1));
            tm1 = fmaxf(tm1, __shfl_xor_sync(0xffffffffu, tm1, 2));
            const float m0n = fmaxf(m0, tm0), m1n = fmaxf(m1, tm1);
            const float a0 = expf(m0 - m0n), a1 = expf(m1 - m1n);
            m0 = m0n; m1 = m1n;
            float rs0 = 0.f, rs1 = 0.f;
            #pragma unroll
            for (int nt = 0; nt < 8; nt++) {
                sf[nt][0] = expf(sf[nt][0] - m0n);
                sf[nt][1] = expf(sf[nt][1] - m0n);
                sf[nt][2] = expf(sf[nt][2] - m1n);
                sf[nt][3] = expf(sf[nt][3] - m1n);
                rs0 += sf[nt][0] + sf[nt][1];
                rs1 += sf[nt][2] + sf[nt][3];
            }
            rs0 += __shfl_xor_sync(0xffffffffu, rs0, 1);
            rs0 += __shfl_xor_sync(0xffffffffu, rs0, 2);
            rs1 += __shfl_xor_sync(0xffffffffu, rs1, 1);
            rs1 += __shfl_xor_sync(0xffffffffu, rs1, 2);
            l0 = a0 * l0 + rs0;
            l1 = a1 * l1 + rs1;
            #pragma unroll
            for (int dt = 0; dt < 8; dt++) {
                oc[dt][0] *= a0; oc[dt][1] *= a0;
                oc[dt][2] *= a1; oc[dt][3] *= a1;
            }
            #pragma unroll
            for (int ki = 0; ki < 4; ki++) {
                uint32_t pa[4];
                pa[0] = pack_h2(sf[2*ki][0],   sf[2*ki][1]);
                pa[1] = pack_h2(sf[2*ki][2],   sf[2*ki][3]);
                pa[2] = pack_h2(sf[2*ki+1][0], sf[2*ki+1][1]);
                pa[3] = pack_h2(sf[2*ki+1][2], sf[2*ki+1][3]);
                #pragma unroll
                for (int dt = 0; dt < 8; dt++) {
                    const int nb = (dt * 8 + g) * VROW + sub * 64 + ki * 16 + tg * 2;
                    uint32_t vb[2];
                    vb[0] = *(const uint32_t*)(VS + nb);
                    vb[1] = *(const uint32_t*)(VS + nb + 8);
                    mma_f16(oc[dt], pa, vb);
                }
            }
        }
        __syncthreads();
        issue(ct + 2, false);
    }

    const float il0 = 1.f / l0, il1 = 1.f / l1;
    #pragma unroll
    for (int dt = 0; dt < 8; dt++) {
        const int dh = hh_ * DHq + dt * 8 + tg * 2;
        *(uint32_t*)(O + ((size_t)r0 * Bq + bb_) * Dq + dh) =
            pack_h2(oc[dt][0] * il0, oc[dt][1] * il0);
        *(uint32_t*)(O + ((size_t)r1 * Bq + bb_) * Dq + dh) =
            pack_h2(oc[dt][2] * il1, oc[dt][3] * il1);
    }
}

// ---------------- LayerNorm -> fp16 plane (+ optional residual+bias init) ----
__global__ void __launch_bounds__(128) ln_kernel(
    const float* __restrict__ x, const float* __restrict__ w,
    const float* __restrict__ b, __half* __restrict__ y,
    const float* __restrict__ b2, float* __restrict__ init)
{
    const int row = blockIdx.x;
    const int t = threadIdx.x;
    const float4 v = ((const float4*)(x + (size_t)row * Dq))[t];
    float s  = v.x + v.y + v.z + v.w;
    float ss = v.x*v.x + v.y*v.y + v.z*v.z + v.w*v.w;
#pragma unroll
    for (int o = 16; o > 0; o >>= 1) {
        s  += __shfl_xor_sync(0xffffffffu, s,  o);
        ss += __shfl_xor_sync(0xffffffffu, ss, o);
    }
    __shared__ float sh[8];
    const int wi = t >> 5, lane = t & 31;
    if (lane == 0) { sh[wi] = s; sh[4 + wi] = ss; }
    __syncthreads();
    s  = sh[0] + sh[1] + sh[2] + sh[3];
    ss = sh[4] + sh[5] + sh[6] + sh[7];
    const float mu  = s * (1.f / Dq);
    const float var = ss * (1.f / Dq) - mu * mu;
    const float rs  = rsqrtf(var + 1e-5f);
    const float4 wv = ((const float4*)w)[t];
    const float4 bv = ((const float4*)b)[t];
    uint2 o;
    o.x = pack_h2((v.x - mu) * rs * wv.x + bv.x, (v.y - mu) * rs * wv.y + bv.y);
    o.y = pack_h2((v.z - mu) * rs * wv.z + bv.z, (v.w - mu) * rs * wv.w + bv.w);
    ((uint2*)(y + (size_t)row * Dq))[t] = o;
    if (init) {
        const float4 b2v = ((const float4*)b2)[t];
        float4 iv;
        iv.x = v.x + b2v.x; iv.y = v.y + b2v.y;
        iv.z = v.z + b2v.z; iv.w = v.w + b2v.w;
        ((float4*)(init + (size_t)row * Dq))[t] = iv;
    }
}

// ---------------- launch ----------------
extern "C" void kernel_launch(void* const* d_in, const int* in_sizes, int n_in,
                              void* d_out, int out_size)
{
    (void)in_sizes; (void)n_in; (void)out_size;
    const float* x    = (const float*)d_in[0];
    const float* edge = (const float*)d_in[1];
    const float* inw  = (const float*)d_in[2];
    const float* inb  = (const float*)d_in[3];
    const float* outw = (const float*)d_in[4];
    const float* outb = (const float*)d_in[5];
    const float* l1w  = (const float*)d_in[6];
    const float* l1b  = (const float*)d_in[7];
    const float* l2w  = (const float*)d_in[8];
    const float* l2b  = (const float*)d_in[9];
    const float* n1w  = (const float*)d_in[10];
    const float* n1b  = (const float*)d_in[11];
    const float* n2w  = (const float*)d_in[12];
    const float* n2b  = (const float*)d_in[13];

    __half *xn,*xn2,*q,*k,*vT,*at,*h1,*w1,*w2,*w3,*w4;
    float *x1;
    cudaGetSymbolAddress((void**)&xn,   g_xn);
    cudaGetSymbolAddress((void**)&xn2,  g_xn2);
    cudaGetSymbolAddress((void**)&q,    g_q);
    cudaGetSymbolAddress((void**)&k,    g_k);
    cudaGetSymbolAddress((void**)&vT,   g_vT);
    cudaGetSymbolAddress((void**)&at,   g_at);
    cudaGetSymbolAddress((void**)&h1,   g_h1);
    cudaGetSymbolAddress((void**)&w1,   g_w1);
    cudaGetSymbolAddress((void**)&w2,   g_w2);
    cudaGetSymbolAddress((void**)&w3,   g_w3);
    cudaGetSymbolAddress((void**)&w4,   g_w4);
    cudaGetSymbolAddress((void**)&x1,   g_x1);

    float* out_x    = (float*)d_out;
    float* edge_out = out_x + (size_t)ROWS * Dq;

    const int PG_SMEM = 2 * 2 * 128 * SROW * (int)sizeof(__half);                    // 40960
    const int FL_SMEM = (128 * QROW + 2 * 128 * QROW + 2 * 64 * VROW) * (int)sizeof(__half); // 90112
    cudaFuncSetAttribute(pg<0>, cudaFuncAttributeMaxDynamicSharedMemorySize, PG_SMEM);
    cudaFuncSetAttribute(pg<4>, cudaFuncAttributeMaxDynamicSharedMemorySize, PG_SMEM);
    cudaFuncSetAttribute(pg<6>, cudaFuncAttributeMaxDynamicSharedMemorySize, PG_SMEM);
    cudaFuncSetAttribute(flash, cudaFuncAttributeMaxDynamicSharedMemorySize, FL_SMEM);

    // 0) all weights -> fp16 in one launch
    to_half_all<<<(W1_N4 + W2_N4 + W3_N4 + W4_N4) / 256, 256>>>(
        inw, outw, l1w, l2w, w1, w2, w3, w4);
    // 1) LN1 (+ init x1 = x + outb, the out-proj atomic target)
    ln_kernel<<<ROWS, 128>>>(x, n1w, n1b, xn, outb, x1);
    // 2) QKV (q,k planes; v transposed)
    pg<0><<<dim3(12, 32, 1), 256, PG_SMEM>>>(xn, w1, inb, nullptr, q, k, vT, Dq, Dq, Dq);
    // 3) fused attention: edge_out + attn plane
    flash<<<dim3(8, BHq), 256, FL_SMEM>>>(q, k, vT, edge, edge_out, at);
    // 4) out projection (split-K x2, atomicAdd into x1)
    pg<6><<<dim3(4, 32, 2), 256, PG_SMEM>>>(at, w2, nullptr, x1, nullptr, nullptr, nullptr,
                                            Dq, Dq, Dq);
    // 5) LN2 (+ init out_x = x1 + l2b, the FFN2 atomic target)
    ln_kernel<<<ROWS, 128>>>(x1, n2w, n2b, xn2, l2b, out_x);
    // 6) FFN1 + GELU
    pg<4><<<dim3(16, 32, 1), 256, PG_SMEM>>>(xn2, w3, l1b, nullptr, h1, nullptr, nullptr,
                                             Dq, Dq, Dq);
    // 7) FFN2 (split-K x2, atomicAdd into out_x)
    pg<6><<<dim3(4, 32, 2), 256, PG_SMEM>>>(h1, w4, nullptr, out_x, nullptr, nullptr, nullptr,
                                            DFFq, DFFq, DFFq);
}